// round 1
// baseline (speedup 1.0000x reference)
#include <cuda_runtime.h>

#define NL 200
#define NH 64
#define SUMS_SZ (NL * NH)

// Scratch (allocation-free): per-dataset segment sums and counts.
__device__ float g_sums[2][SUMS_SZ];
__device__ float g_cnts[2][NL];

__global__ void zero_kernel() {
    int i = blockIdx.x * blockDim.x + threadIdx.x;
    if (i < SUMS_SZ) { g_sums[0][i] = 0.f; g_sums[1][i] = 0.f; }
    if (i < NL)      { g_cnts[0][i] = 0.f; g_cnts[1][i] = 0.f; }
}

// grid (NBLK, 2): y = dataset. Block privatizes [200][64] sums + [200] counts
// in dynamic smem, flushes once with float4 global atomics.
__global__ __launch_bounds__(512, 4)
void accum_kernel(const float* __restrict__ lat0, const int* __restrict__ lab0,
                  const float* __restrict__ lat1, const int* __restrict__ lab1,
                  int n_rows, int rows_per_block)
{
    extern __shared__ float smem[];
    float* s_sums = smem;            // SUMS_SZ floats
    float* s_cnt  = smem + SUMS_SZ;  // NL floats

    const int ds = blockIdx.y;
    const float* __restrict__ lat = ds ? lat1 : lat0;
    const int*   __restrict__ lab = ds ? lab1 : lab0;

    for (int i = threadIdx.x; i < SUMS_SZ; i += blockDim.x) s_sums[i] = 0.f;
    for (int i = threadIdx.x; i < NL; i += blockDim.x) s_cnt[i] = 0.f;
    __syncthreads();

    const int lane = threadIdx.x & 31;
    const int wid  = threadIdx.x >> 5;
    const int nw   = blockDim.x >> 5;

    int r0 = blockIdx.x * rows_per_block;
    int r1 = r0 + rows_per_block; if (r1 > n_rows) r1 = n_rows;

    // One warp per row; lane k handles cols k and k+32 (conflict-free smem atomics).
    // 2-row unroll to batch LDGs (MLP).
    int r = r0 + wid;
    for (; r + nw < r1; r += 2 * nw) {
        int ra = r, rb = r + nw;
        int la = __ldg(lab + ra);
        int lb = __ldg(lab + rb);
        float a0 = __ldg(lat + ra * NH + lane);
        float a1 = __ldg(lat + ra * NH + lane + 32);
        float b0 = __ldg(lat + rb * NH + lane);
        float b1 = __ldg(lat + rb * NH + lane + 32);
        atomicAdd(s_sums + la * NH + lane,      a0);
        atomicAdd(s_sums + la * NH + lane + 32, a1);
        if (lane == 0) atomicAdd(s_cnt + la, 1.f);
        atomicAdd(s_sums + lb * NH + lane,      b0);
        atomicAdd(s_sums + lb * NH + lane + 32, b1);
        if (lane == 0) atomicAdd(s_cnt + lb, 1.f);
    }
    if (r < r1) {
        int la = __ldg(lab + r);
        float a0 = __ldg(lat + r * NH + lane);
        float a1 = __ldg(lat + r * NH + lane + 32);
        atomicAdd(s_sums + la * NH + lane,      a0);
        atomicAdd(s_sums + la * NH + lane + 32, a1);
        if (lane == 0) atomicAdd(s_cnt + la, 1.f);
    }
    __syncthreads();

    // Flush with vector atomics (sm_90+ float4 atomicAdd).
    float4* gs = reinterpret_cast<float4*>(g_sums[ds]);
    const float4* ss = reinterpret_cast<const float4*>(s_sums);
    for (int i = threadIdx.x; i < SUMS_SZ / 4; i += blockDim.x)
        atomicAdd(gs + i, ss[i]);
    for (int i = threadIdx.x; i < NL; i += blockDim.x)
        atomicAdd(&g_cnts[ds][i], s_cnt[i]);
}

// Single block: reset check, centroid update, MSE + KL -> scalar.
__global__ void finalize_kernel(const float* __restrict__ cent_p,
                                const float* __restrict__ pcnt,
                                const float* __restrict__ cent_t,
                                const float* __restrict__ tcnt,
                                const float* __restrict__ ncells,
                                float* __restrict__ out)
{
    __shared__ float red[256];
    __shared__ float s_n[2][NL];    // segment counts n
    __shared__ float s_c[2][NL];    // old counts (post-reset for pseudo)
    __shared__ float s_new[2][NL];  // updated counts
    int t = threadIdx.x;

    // reset pseudo_count if max >= NCELLS_MAX (= 200 * 1000)
    red[t] = (t < NL) ? pcnt[t] : -1e30f;
    __syncthreads();
    for (int s = 128; s > 0; s >>= 1) { if (t < s) red[t] = fmaxf(red[t], red[t + s]); __syncthreads(); }
    bool reset = (red[0] >= 200000.0f);
    __syncthreads();

    if (t < NL) {
        float n0 = g_cnts[0][t];
        float c0 = reset ? 1.0f : pcnt[t];
        s_n[0][t] = n0; s_c[0][t] = c0;
        s_new[0][t] = (n0 > 5.0f) ? (c0 + n0) : c0;
        float n1 = g_cnts[1][t];
        float c1 = tcnt[t];
        s_n[1][t] = n1; s_c[1][t] = c1;
        s_new[1][t] = (n1 > 5.0f) ? (c1 + n1) : c1;
    }
    __syncthreads();

    // MSE over updated centroids. centroids layout [H, L]: i = h*200 + l.
    // sums layout [L, H]: l*64 + h. means.T * n == sums (exact for n >= 1).
    float acc = 0.f;
    for (int i = t; i < SUMS_SZ; i += 256) {
        int h = i / NL, l = i - h * NL;
        float cp = cent_p[i];
        float n0 = s_n[0][l];
        if (n0 > 5.0f) { float c0 = s_c[0][l]; cp = (cp * c0 + g_sums[0][l * NH + h]) / (c0 + n0); }
        float ct = cent_t[i];
        float n1 = s_n[1][l];
        if (n1 > 5.0f) { float c1 = s_c[1][l]; ct = (ct * c1 + g_sums[1][l * NH + h]) / (c1 + n1); }
        float d = cp - ct;
        acc += d * d;
    }

    // S = sum of updated pseudo counts
    red[t] = (t < NL) ? s_new[0][t] : 0.f;
    __syncthreads();
    for (int s = 128; s > 0; s >>= 1) { if (t < s) red[t] += red[t + s]; __syncthreads(); }
    float S = red[0];
    __syncthreads();

    float kl = 0.f;
    if (t < NL) {
        float p = s_new[0][t] / S;
        kl = p * (logf(p) - logf(ncells[t]));
    }

    red[t] = acc;
    __syncthreads();
    for (int s = 128; s > 0; s >>= 1) { if (t < s) red[t] += red[t + s]; __syncthreads(); }
    float mse_sum = red[0];
    __syncthreads();
    red[t] = kl;
    __syncthreads();
    for (int s = 128; s > 0; s >>= 1) { if (t < s) red[t] += red[t + s]; __syncthreads(); }
    if (t == 0) out[0] = mse_sum / (float)SUMS_SZ + red[0] / (float)NL;
}

extern "C" void kernel_launch(void* const* d_in, const int* in_sizes, int n_in,
                              void* d_out, int out_size)
{
    const float* p_lat  = (const float*)d_in[0];
    const int*   p_lab  = (const int*)  d_in[1];
    const float* t_lat  = (const float*)d_in[2];
    const int*   t_lab  = (const int*)  d_in[3];
    const float* cent_p = (const float*)d_in[4];
    const float* p_cnt  = (const float*)d_in[5];
    const float* cent_t = (const float*)d_in[6];
    const float* t_cnt  = (const float*)d_in[7];
    const float* ncells = (const float*)d_in[8];
    int n_rows = in_sizes[1];  // 1,000,000

    const int smem_bytes = (SUMS_SZ + NL) * (int)sizeof(float);
    cudaFuncSetAttribute(accum_kernel, cudaFuncAttributeMaxDynamicSharedMemorySize, smem_bytes);

    zero_kernel<<<(SUMS_SZ + 255) / 256, 256>>>();

    const int nblk = 296;  // 2 CTAs/SM per dataset -> 4 resident CTAs/SM total
    int rpb = (n_rows + nblk - 1) / nblk;
    dim3 grid(nblk, 2);
    accum_kernel<<<grid, 512, smem_bytes>>>(p_lat, p_lab, t_lat, t_lab, n_rows, rpb);

    finalize_kernel<<<1, 256>>>(cent_p, p_cnt, cent_t, t_cnt, ncells, (float*)d_out);
}